// round 14
// baseline (speedup 1.0000x reference)
#include <cuda_runtime.h>
#include <cuda_fp16.h>

#define HH 1024
#define WW 1024
#define NPIX (HH * WW)

// Persistent device-global scratch (no cudaMalloc allowed).
__device__ uint2  g_Ph[NPIX];   // 4 fp16 weights (up,dn,lf,rt) per pixel; zeros at seeds
__device__ float2 g_buf[NPIX];  // ping-pong partner of d_out

__global__ __launch_bounds__(256)
void rw_setup_kernel(const float* __restrict__ img,
                     const int* __restrict__ seeds,
                     float2* __restrict__ x0)
{
    int j = blockIdx.x * 32 + threadIdx.x;
    int i = blockIdx.y * blockDim.y + threadIdx.y;
    int idx = i * WW + j;

    float c  = img[idx];
    bool  cb = (c > 0.1f);

    const int di[4] = {-1, 1, 0, 0};
    const int dj[4] = { 0, 0,-1, 1};

    float w[4];
    float rowsum = 0.0f;
#pragma unroll
    for (int d = 0; d < 4; d++) {
        int ni = i + di[d], nj = j + dj[d];
        bool valid = (ni >= 0) && (ni < HH) && (nj >= 0) && (nj < WW);
        int nidx = (valid ? ni : i) * WW + (valid ? nj : j);
        float nb = img[nidx];
        float same = ((nb > 0.1f) != cb) ? 1.0f : 0.0f;
        float diff = c - nb + same;
        float wt = valid ? expf(-1.0f - fabsf(diff)) : 0.0f;
        w[d] = wt;
        rowsum += wt;
    }
    float inv = 1.0f / rowsum;

    int s = seeds[idx];
    uint2 ph = make_uint2(0u, 0u);
    if (!s) {
        __half2 h01 = __floats2half2_rn(w[0] * inv, w[1] * inv);
        __half2 h23 = __floats2half2_rn(w[2] * inv, w[3] * inv);
        ph.x = *reinterpret_cast<unsigned*>(&h01);
        ph.y = *reinterpret_cast<unsigned*>(&h23);
    }
    g_Ph[idx] = ph;

    float2 x;
    x.x = (s == 1) ? 1.0f : 0.0f;
    x.y = (s == 2) ? 1.0f : 0.0f;
    x0[idx] = x;
}

// ---------------------------------------------------------------------------
// Four Jacobi steps per launch, tile 32x32, 128 threads, 10 blocks/SM
// (single wave: 1024 <= 148*10). Each thread computes a 2x2 QUAD of pixels:
// 12 smem reads per 4 px (vs 16 for pairs) -> 25% fewer LDS bytes/instrs.
// Phase 0 reads x straight from global. P fp16 (uint2) from L2, fp32 math,
// self = 1 - sum(p) keeps rows exactly stochastic.
//   sA: 38x38 logical origin (by-3, bx-3)   sB: 36x36 origin (by-2, bx-2)
//   p0: global->sA (R=3)  p1: sA->sB (R=2)  p2: sB->sA (R=1)  p3: sA->global
// ---------------------------------------------------------------------------
#define TX 32
#define TY 32
#define NTHR 128
#define SA 38
#define SB 36

__device__ __forceinline__
void unpack_p(uint2 ph, float2& w01, float2& w23)
{
    w01 = __half22float2(*reinterpret_cast<__half2*>(&ph.x));  // (up, dn)
    w23 = __half22float2(*reinterpret_cast<__half2*>(&ph.y));  // (lf, rt)
}

// out = p.up*up + p.dn*dn + p.lf*lf + p.rt*rt + self*ct   (both channels)
__device__ __forceinline__
float2 stencil(float2 pud, float2 plr, float2 up, float2 dn,
               float2 lf, float2 rt, float2 ct)
{
    float s = 1.0f - ((pud.x + pud.y) + (plr.x + plr.y));
    float2 o;
    o.x = pud.x*up.x + pud.y*dn.x + plr.x*lf.x + plr.y*rt.x + s*ct.x;
    o.y = pud.x*up.y + pud.y*dn.y + plr.x*lf.y + plr.y*rt.y + s*ct.y;
    return o;
}

// One Jacobi sub-step over a DxD output region, one 2x2 quad per thread.
// in_log/out_log point at logical pixel (by, bx) of their buffers.
//  D: region side (even)  R: region radius  SI/SO: strides
//  GUARD: coords may leave image   GIN: input is global memory
template<int D, int R, int SI, int SO, bool GUARD, bool GIN>
__device__ __forceinline__
void quad_phase(int tid, int by, int bx,
                const float2* __restrict__ in_log,
                float2* __restrict__ out_log)
{
    constexpr int QD    = D / 2;
    constexpr int TOT   = QD * QD;
    constexpr int NITER = (TOT + NTHR - 1) / NTHR;
    constexpr bool EXACT = (NITER * NTHR == TOT);

    for (int it = 0; it < NITER; it++) {
        int e = tid + it * NTHR;
        if (EXACT || e < TOT) {
            int qr = e / QD;
            int qc = e - qr * QD;
            int ro = 2 * qr - R;   // logical row of quad's top px
            int co = 2 * qc - R;   // logical col of quad's left px

            // ---- P loads first (deep MLP; L2-resident, fp16) ----
            const uint2* pp = g_Ph + (by + ro) * WW + (bx + co);
            uint2 h00, h01, h10, h11;
            if (GUARD) {
                bool vy0 = (unsigned)(by + ro)     < HH;
                bool vy1 = (unsigned)(by + ro + 1) < HH;
                bool vx0 = (unsigned)(bx + co)     < WW;
                bool vx1 = (unsigned)(bx + co + 1) < WW;
                const uint2 z = make_uint2(0u, 0u);
                h00 = (vy0 && vx0) ? pp[0]      : z;
                h01 = (vy0 && vx1) ? pp[1]      : z;
                h10 = (vy1 && vx0) ? pp[WW]     : z;
                h11 = (vy1 && vx1) ? pp[WW + 1] : z;
            } else {
                h00 = pp[0];
                h01 = pp[1];
                h10 = pp[WW];
                h11 = pp[WW + 1];
            }

            // ---- x reads: 12 values for the 2x2 quad ----
            const float2* ip = in_log + ro * SI + co;
            float2 up0, up1, dn0, dn1, lf0, lf1, rt0, rt1;
            float2 c00, c01, c10, c11;
            if (GIN && GUARD) {
                bool vx0 = (unsigned)(bx + co)     < WW;
                bool vx1 = (unsigned)(bx + co + 1) < WW;
                bool vxl = (unsigned)(bx + co - 1) < WW;
                bool vxr = (unsigned)(bx + co + 2) < WW;
                bool vym = (unsigned)(by + ro - 1) < HH;
                bool vy0 = (unsigned)(by + ro)     < HH;
                bool vy1 = (unsigned)(by + ro + 1) < HH;
                bool vy2 = (unsigned)(by + ro + 2) < HH;
                const float2 z = make_float2(0.f, 0.f);
                up0 = (vym && vx0) ? ip[-SI]         : z;
                up1 = (vym && vx1) ? ip[-SI + 1]     : z;
                c00 = (vy0 && vx0) ? ip[0]           : z;
                c01 = (vy0 && vx1) ? ip[1]           : z;
                c10 = (vy1 && vx0) ? ip[SI]          : z;
                c11 = (vy1 && vx1) ? ip[SI + 1]      : z;
                dn0 = (vy2 && vx0) ? ip[2 * SI]      : z;
                dn1 = (vy2 && vx1) ? ip[2 * SI + 1]  : z;
                lf0 = (vy0 && vxl) ? ip[-1]          : z;
                lf1 = (vy1 && vxl) ? ip[SI - 1]      : z;
                rt0 = (vy0 && vxr) ? ip[2]           : z;
                rt1 = (vy1 && vxr) ? ip[SI + 2]      : z;
            } else {
                up0 = ip[-SI];
                up1 = ip[-SI + 1];
                c00 = ip[0];
                c01 = ip[1];
                c10 = ip[SI];
                c11 = ip[SI + 1];
                dn0 = ip[2 * SI];
                dn1 = ip[2 * SI + 1];
                lf0 = ip[-1];
                lf1 = ip[SI - 1];
                rt0 = ip[2];
                rt1 = ip[SI + 2];
            }

            float2 pud, plr;
            unpack_p(h00, pud, plr);
            float2 o00 = stencil(pud, plr, up0, c10, lf0, c01, c00);
            unpack_p(h01, pud, plr);
            float2 o01 = stencil(pud, plr, up1, c11, c00, rt0, c01);
            unpack_p(h10, pud, plr);
            float2 o10 = stencil(pud, plr, c00, dn0, lf1, c11, c10);
            unpack_p(h11, pud, plr);
            float2 o11 = stencil(pud, plr, c01, dn1, c10, rt1, c11);

            float2* op = out_log + ro * SO + co;
            op[0]      = o00;
            op[1]      = o01;
            op[SO]     = o10;
            op[SO + 1] = o11;
        }
    }
}

template<bool GUARD>
__device__ __forceinline__
void rw_body(int tid, int by, int bx,
             const float2* __restrict__ xin, float2* __restrict__ xout,
             float2* __restrict__ sAl, float2* __restrict__ sBl)
{
    const float2* gin  = xin  + by * WW + bx;
    float2*       gout = xout + by * WW + bx;

    quad_phase<38, 3, WW, SA, GUARD, true >(tid, by, bx, gin, sAl);   // global -> sA
    __syncthreads();
    quad_phase<36, 2, SA, SB, GUARD, false>(tid, by, bx, sAl, sBl);   // sA -> sB
    __syncthreads();
    quad_phase<34, 1, SB, SA, GUARD, false>(tid, by, bx, sBl, sAl);   // sB -> sA
    __syncthreads();
    // final tile is fully in-image -> never guarded
    quad_phase<32, 0, SA, WW, false, false>(tid, by, bx, sAl, gout);  // sA -> global
}

__global__ __launch_bounds__(NTHR, 10)
void rw_step4_kernel(const float2* __restrict__ xin,
                     float2* __restrict__ xout)
{
    __shared__ float2 sA[SA * SA];  // 11.55 KB
    __shared__ float2 sB[SB * SB];  // 10.4 KB

    const int tid = threadIdx.x;
    const int bx  = blockIdx.x * TX;
    const int by  = blockIdx.y * TY;

    float2* sAl = sA + 3 * SA + 3;  // logical (by, bx)
    float2* sBl = sB + 2 * SB + 2;

    // p0 touches x rows by-4..by+35, cols bx-4..bx+35
    const bool interior = (bx >= 4) && (bx + 36 <= WW) &&
                          (by >= 4) && (by + 36 <= HH);
    if (interior) rw_body<false>(tid, by, bx, xin, xout, sAl, sBl);
    else          rw_body<true >(tid, by, bx, xin, xout, sAl, sBl);
}

extern "C" void kernel_launch(void* const* d_in, const int* in_sizes, int n_in,
                              void* d_out, int out_size)
{
    const float* img   = (const float*)d_in[0];
    const int*   seeds = (const int*)d_in[1];
    float2*      A     = (float2*)d_out;

    float2* B = nullptr;
    cudaGetSymbolAddress((void**)&B, g_buf);

    {
        dim3 blk(32, 8);
        dim3 grd(WW / 32, HH / 8);
        // x0 written into B; 25 quad-step kernels alternate B->A->B...,
        // t=24 (even) writes A = d_out.
        rw_setup_kernel<<<grd, blk>>>(img, seeds, B);
    }

    dim3 blk(NTHR);
    dim3 grd(WW / TX, HH / TY);   // 32 x 32 = 1024 blocks
    for (int t = 0; t < 25; t++) {
        const float2* xin  = (t & 1) ? A : B;
        float2*       xout = (t & 1) ? B : A;
        rw_step4_kernel<<<grd, blk>>>(xin, xout);
    }
}

// round 15
// speedup vs baseline: 1.4724x; 1.4724x over previous
#include <cuda_runtime.h>
#include <cuda_fp16.h>

#define HH 1024
#define WW 1024
#define NPIX (HH * WW)

// Persistent device-global scratch (no cudaMalloc allowed).
__device__ uint2   g_Ph[NPIX];    // 4 fp16 weights (up,dn,lf,rt) per pixel; zeros at seeds
__device__ __half2 g_bufAh[NPIX]; // fp16 state ping
__device__ __half2 g_bufBh[NPIX]; // fp16 state pong

__global__ __launch_bounds__(256)
void rw_setup_kernel(const float* __restrict__ img,
                     const int* __restrict__ seeds,
                     __half2* __restrict__ x0)
{
    int j = blockIdx.x * 32 + threadIdx.x;
    int i = blockIdx.y * blockDim.y + threadIdx.y;
    int idx = i * WW + j;

    float c  = img[idx];
    bool  cb = (c > 0.1f);

    const int di[4] = {-1, 1, 0, 0};
    const int dj[4] = { 0, 0,-1, 1};

    float w[4];
    float rowsum = 0.0f;
#pragma unroll
    for (int d = 0; d < 4; d++) {
        int ni = i + di[d], nj = j + dj[d];
        bool valid = (ni >= 0) && (ni < HH) && (nj >= 0) && (nj < WW);
        int nidx = (valid ? ni : i) * WW + (valid ? nj : j);
        float nb = img[nidx];
        float same = ((nb > 0.1f) != cb) ? 1.0f : 0.0f;
        float diff = c - nb + same;
        float wt = valid ? expf(-1.0f - fabsf(diff)) : 0.0f;
        w[d] = wt;
        rowsum += wt;
    }
    float inv = 1.0f / rowsum;

    int s = seeds[idx];
    uint2 ph = make_uint2(0u, 0u);
    if (!s) {
        __half2 h01 = __floats2half2_rn(w[0] * inv, w[1] * inv);
        __half2 h23 = __floats2half2_rn(w[2] * inv, w[3] * inv);
        ph.x = *reinterpret_cast<unsigned*>(&h01);
        ph.y = *reinterpret_cast<unsigned*>(&h23);
    }
    g_Ph[idx] = ph;

    // one-hot seed probabilities, exact in fp16 (0 and 1 representable)
    x0[idx] = __floats2half2_rn((s == 1) ? 1.0f : 0.0f,
                                (s == 2) ? 1.0f : 0.0f);
}

// ---------------------------------------------------------------------------
// Four Jacobi steps per launch, tile 32x32, 256 threads, 8 blocks/SM single
// wave. Vertical-pair threads (2 px/thread). State x in fp16 (__half2 packs
// both classes, 4 B/px): halves all LDS/STS/x-LDG bytes. Arithmetic in fp32
// (unpack -> stencil -> pack); self = 1 - sum(p) in fp32 keeps rows exactly
// stochastic (no drift). Final kernel's last phase writes fp32 to d_out.
//   sA: 38x38 logical origin (by-3, bx-3)   sB: 36x36 origin (by-2, bx-2)
//   p0: global->sA (R=3)  p1: sA->sB (R=2)  p2: sB->sA (R=1)  p3: sA->global
// ---------------------------------------------------------------------------
#define TX 32
#define TY 32
#define SA 38
#define SB 36

__device__ __forceinline__
void unpack_p(uint2 ph, float2& w01, float2& w23)
{
    w01 = __half22float2(*reinterpret_cast<__half2*>(&ph.x));  // (up, dn)
    w23 = __half22float2(*reinterpret_cast<__half2*>(&ph.y));  // (lf, rt)
}

__device__ __forceinline__ void store_px(__half2* p, float2 o) {
    *p = __floats2half2_rn(o.x, o.y);
}
__device__ __forceinline__ void store_px(float2* p, float2 o) {
    *p = o;
}

// One Jacobi sub-step over a DxD output region, 2 vertically-adjacent px per
// thread. in_log/out_log point at logical pixel (by, bx) of their buffers.
//  D: region side (even)  R: region radius  SI/SO: strides
//  GUARD: coords may leave image   GIN: input is global memory
template<int D, int R, int SI, int SO, bool GUARD, bool GIN, typename OutT>
__device__ __forceinline__
void pair_phase(int tid, int by, int bx,
                const __half2* __restrict__ in_log,
                OutT* __restrict__ out_log)
{
    constexpr int TOT   = D * (D / 2);
    constexpr int NITER = (TOT + 255) / 256;
    constexpr bool EXACT = (NITER * 256 == TOT);

    for (int it = 0; it < NITER; it++) {
        int e = tid + it * 256;
        if (EXACT || e < TOT) {
            int pr = e / D;
            int cc = e - pr * D;
            int ro = 2 * pr - R;   // logical row of first output px
            int co = cc - R;       // logical col

            // --- P loads first (deep MLP; L2-resident, fp16) ---
            const uint2* pp = g_Ph + (by + ro) * WW + (bx + co);
            uint2 ph1, ph2;
            if (GUARD) {
                bool vc = (unsigned)(bx + co) < WW;
                ph1 = (vc && (unsigned)(by + ro)     < HH) ? pp[0]  : make_uint2(0u, 0u);
                ph2 = (vc && (unsigned)(by + ro + 1) < HH) ? pp[WW] : make_uint2(0u, 0u);
            } else {
                ph1 = pp[0];
                ph2 = pp[WW];
            }

            // --- x reads (fp16): 4-row center column + lf/rt for both rows ---
            const __half2* ip = in_log + ro * SI + co;
            __half2 ha, hb, hc, hd, hl0, hr0, hl1, hr1;
            if (GIN && GUARD) {
                bool vc  = (unsigned)(bx + co)     < WW;
                bool vcl = (unsigned)(bx + co - 1) < WW;
                bool vcr = (unsigned)(bx + co + 1) < WW;
                bool vym = (unsigned)(by + ro - 1) < HH;
                bool vy0 = (unsigned)(by + ro)     < HH;
                bool vy1 = (unsigned)(by + ro + 1) < HH;
                bool vy2 = (unsigned)(by + ro + 2) < HH;
                const __half2 z = __float2half2_rn(0.f);
                ha  = (vym && vc ) ? ip[-SI]     : z;
                hb  = (vy0 && vc ) ? ip[0]       : z;
                hc  = (vy1 && vc ) ? ip[SI]      : z;
                hd  = (vy2 && vc ) ? ip[2 * SI]  : z;
                hl0 = (vy0 && vcl) ? ip[-1]      : z;
                hr0 = (vy0 && vcr) ? ip[1]       : z;
                hl1 = (vy1 && vcl) ? ip[SI - 1]  : z;
                hr1 = (vy1 && vcr) ? ip[SI + 1]  : z;
            } else {
                ha  = ip[-SI];
                hb  = ip[0];
                hc  = ip[SI];
                hd  = ip[2 * SI];
                hl0 = ip[-1];
                hr0 = ip[1];
                hl1 = ip[SI - 1];
                hr1 = ip[SI + 1];
            }

            float2 a   = __half22float2(ha);
            float2 b   = __half22float2(hb);
            float2 c   = __half22float2(hc);
            float2 d   = __half22float2(hd);
            float2 lf0 = __half22float2(hl0);
            float2 rt0 = __half22float2(hr0);
            float2 lf1 = __half22float2(hl1);
            float2 rt1 = __half22float2(hr1);

            float2 p1a, p1b, p2a, p2b;
            unpack_p(ph1, p1a, p1b);   // p1a=(up,dn) p1b=(lf,rt)
            unpack_p(ph2, p2a, p2b);

            float s1 = 1.0f - ((p1a.x + p1a.y) + (p1b.x + p1b.y));
            float s2 = 1.0f - ((p2a.x + p2a.y) + (p2b.x + p2b.y));
            float2 o0, o1;
            o0.x = p1a.x*a.x + p1a.y*c.x + p1b.x*lf0.x + p1b.y*rt0.x + s1*b.x;
            o0.y = p1a.x*a.y + p1a.y*c.y + p1b.x*lf0.y + p1b.y*rt0.y + s1*b.y;
            o1.x = p2a.x*b.x + p2a.y*d.x + p2b.x*lf1.x + p2b.y*rt1.x + s2*c.x;
            o1.y = p2a.x*b.y + p2a.y*d.y + p2b.x*lf1.y + p2b.y*rt1.y + s2*c.y;

            store_px(out_log + ro * SO + co,       o0);
            store_px(out_log + (ro + 1) * SO + co, o1);
        }
    }
}

// LAST: final 4-step kernel -> p3 writes fp32 to d_out (no terminal rounding)
template<bool GUARD, bool LAST>
__device__ __forceinline__
void rw_body(int tid, int by, int bx,
             const __half2* __restrict__ xin,
             __half2* __restrict__ xouth, float2* __restrict__ xoutf,
             __half2* __restrict__ sAl, __half2* __restrict__ sBl)
{
    const __half2* gin = xin + by * WW + bx;

    pair_phase<38, 3, WW, SA, GUARD, true >(tid, by, bx, gin, sAl);   // global -> sA
    __syncthreads();
    pair_phase<36, 2, SA, SB, GUARD, false>(tid, by, bx, sAl, sBl);   // sA -> sB
    __syncthreads();
    pair_phase<34, 1, SB, SA, GUARD, false>(tid, by, bx, sBl, sAl);   // sB -> sA
    __syncthreads();
    // final tile is fully in-image -> never guarded
    if (LAST) {
        pair_phase<32, 0, SA, WW, false, false>(tid, by, bx, sAl,
                                                xoutf + by * WW + bx);
    } else {
        pair_phase<32, 0, SA, WW, false, false>(tid, by, bx, sAl,
                                                xouth + by * WW + bx);
    }
}

template<bool LAST>
__global__ __launch_bounds__(256, 8)
void rw_step4_kernel(const __half2* __restrict__ xin,
                     __half2* __restrict__ xouth,
                     float2* __restrict__ xoutf)
{
    __shared__ __half2 sA[SA * SA];  // 5.8 KB
    __shared__ __half2 sB[SB * SB];  // 5.2 KB

    const int tid = threadIdx.x;
    const int bx  = blockIdx.x * TX;
    const int by  = blockIdx.y * TY;

    __half2* sAl = sA + 3 * SA + 3;  // logical (by, bx)
    __half2* sBl = sB + 2 * SB + 2;

    const bool interior = (bx >= 4) && (bx + 36 <= WW) &&
                          (by >= 4) && (by + 36 <= HH);
    if (interior) rw_body<false, LAST>(tid, by, bx, xin, xouth, xoutf, sAl, sBl);
    else          rw_body<true,  LAST>(tid, by, bx, xin, xouth, xoutf, sAl, sBl);
}

extern "C" void kernel_launch(void* const* d_in, const int* in_sizes, int n_in,
                              void* d_out, int out_size)
{
    const float* img   = (const float*)d_in[0];
    const int*   seeds = (const int*)d_in[1];
    float2*      OUT   = (float2*)d_out;

    __half2 *Ah = nullptr, *Bh = nullptr;
    cudaGetSymbolAddress((void**)&Ah, g_bufAh);
    cudaGetSymbolAddress((void**)&Bh, g_bufBh);

    {
        dim3 blk(32, 8);
        dim3 grd(WW / 32, HH / 8);
        // x0 (fp16) written into Bh; 25 quad-step kernels alternate
        // Bh->Ah->Bh...; t=24 (even, reads Bh) writes fp32 to d_out.
        rw_setup_kernel<<<grd, blk>>>(img, seeds, Bh);
    }

    dim3 blk(256);
    dim3 grd(WW / TX, HH / TY);   // 32 x 32 = 1024 blocks
    for (int t = 0; t < 24; t++) {
        const __half2* xin  = (t & 1) ? Ah : Bh;
        __half2*       xout = (t & 1) ? Bh : Ah;
        rw_step4_kernel<false><<<grd, blk>>>(xin, xout, nullptr);
    }
    // t = 24: reads Bh, writes fp32 result to d_out
    rw_step4_kernel<true><<<grd, blk>>>(Bh, nullptr, OUT);
}